// round 16
// baseline (speedup 1.0000x reference)
#include <cuda_runtime.h>
#include <cuda_fp16.h>
#include <cstdint>

// ===========================================================================
// Problem constants: B=32, N=512, C=1024, H=16, HD=64, SCALE=0.125
// compute_103 toolchain: no tcgen05; tensor cores via mma.sync (HMMA).
// Precision: ALL GEMMs 1-pass fp16 (measured rel_err 5.73e-4; gate 1e-3).
// This round: GEMM warp tile 64x32 -> 64x64 (4 MMA per ldsm instead of 2.67),
// CTA 128 threads (2x2 warps), 2 CTAs/SM, BK=64, single-barrier pipeline.
// ===========================================================================

__device__ __half g_q[16777216];                     // Q (pre-scaled 0.125)
__device__ __half g_k[16777216], g_v[16777216];
__device__ __half g_x16[16777216];                   // x [16384,1024] fp16
__device__ __half g_wq[3145728];                     // W_qkv fp16
__device__ __half g_wp[1048576];                     // W_proj fp16
__device__ __half g_ao[16777216];                    // attn out [B,N,C] fp16

// ---------------------------------------------------------------------------
// PTX helpers (plain sm_80+ PTX — safe under compute_103)
// ---------------------------------------------------------------------------
__device__ __forceinline__ uint32_t smem_u32(const void* p) {
    uint32_t a;
    asm("{ .reg .u64 t; cvta.to.shared.u64 t, %1; cvt.u32.u64 %0, t; }" : "=r"(a) : "l"(p));
    return a;
}
__device__ __forceinline__ void mma_f16(float* c, const uint32_t* a, const uint32_t* b) {
    asm volatile(
        "mma.sync.aligned.m16n8k16.row.col.f32.f16.f16.f32 "
        "{%0,%1,%2,%3}, {%4,%5,%6,%7}, {%8,%9}, {%0,%1,%2,%3};"
        : "+f"(c[0]), "+f"(c[1]), "+f"(c[2]), "+f"(c[3])
        : "r"(a[0]), "r"(a[1]), "r"(a[2]), "r"(a[3]), "r"(b[0]), "r"(b[1]));
}
__device__ __forceinline__ void ldsm_x4(uint32_t* r, uint32_t addr) {
    asm volatile("ldmatrix.sync.aligned.m8n8.x4.shared.b16 {%0,%1,%2,%3}, [%4];"
        : "=r"(r[0]), "=r"(r[1]), "=r"(r[2]), "=r"(r[3]) : "r"(addr));
}
__device__ __forceinline__ void ldsm_x4_b(uint32_t* r0, uint32_t* r1, uint32_t addr) {
    asm volatile("ldmatrix.sync.aligned.m8n8.x4.shared.b16 {%0,%1,%2,%3}, [%4];"
        : "=r"(r0[0]), "=r"(r0[1]), "=r"(r1[0]), "=r"(r1[1]) : "r"(addr));
}
__device__ __forceinline__ void ldsm_x4_t(uint32_t* r, uint32_t addr) {
    asm volatile("ldmatrix.sync.aligned.m8n8.x4.trans.shared.b16 {%0,%1,%2,%3}, [%4];"
        : "=r"(r[0]), "=r"(r[1]), "=r"(r[2]), "=r"(r[3]) : "r"(addr));
}
__device__ __forceinline__ void cp16(uint32_t saddr, const void* g) {
    asm volatile("cp.async.cg.shared.global [%0], [%1], 16;" :: "r"(saddr), "l"(g));
}
#define CP_COMMIT() asm volatile("cp.async.commit_group;" ::: "memory")
#define CP_WAIT0()  asm volatile("cp.async.wait_group 0;" ::: "memory")

__device__ __forceinline__ uint32_t pack_h16(float a, float b) {
    __half2 p = __floats2half2_rn(a, b);
    return *(uint32_t*)&p;
}

// ---------------------------------------------------------------------------
// fp32 -> fp16, all three inputs in one launch (range dispatch)
// ---------------------------------------------------------------------------
#define N4_X  4194304
#define N4_WQ 786432
#define N4_WP 262144
__global__ __launch_bounds__(256)
void cvt_all(const float* __restrict__ x,  const float* __restrict__ wq,
             const float* __restrict__ wp)
{
    int i = blockIdx.x * blockDim.x + threadIdx.x;
    const float* src; __half* dst; int j;
    if (i < N4_X)                 { src = x;  dst = g_x16; j = i; }
    else if (i < N4_X + N4_WQ)    { src = wq; dst = g_wq;  j = i - N4_X; }
    else if (i < N4_X + N4_WQ + N4_WP) { src = wp; dst = g_wp; j = i - N4_X - N4_WQ; }
    else return;
    float4 v = ((const float4*)src)[j];
    ((uint32_t*)dst)[2*j]   = pack_h16(v.x, v.y);
    ((uint32_t*)dst)[2*j+1] = pack_h16(v.z, v.w);
}

// ---------------------------------------------------------------------------
// HMMA GEMM (1-pass fp16): C[m,n] = sum_k A[m,k]*B[n,k]. K=1024.
// CTA 128x128, BK=64, 128 threads, 4 warps (2m x 2n), 64x64 per warp.
// Single __syncthreads per chunk: wait0 -> bar -> issue next loads -> compute.
// mode 0: scatter to q/k/v fp16. mode 1: +bias -> Cout fp32.
// ---------------------------------------------------------------------------
#define PK 72                        // 64 + 8 pad halves per row
#define MATB (128 * PK * 2)          // 18432 B per 128x64 tile
#define BUFB (2 * MATB)              // A + B tiles: 36864 B
#define GSMEM (2 * BUFB)             // double buffered: 73728 B
#define NCHUNK 16

__global__ __launch_bounds__(128, 2)
void hmma_gemm(const __half* __restrict__ Ah, const __half* __restrict__ Bs,
               const float* __restrict__ bias, float* __restrict__ Cout, int mode)
{
    extern __shared__ char smem[];
    const uint32_t sb = smem_u32(smem);
    const int tid  = threadIdx.x;
    const int wid  = tid >> 5, lane = tid & 31;
    const int wm   = wid >> 1, wn = wid & 1;          // 2 x 2 warp grid, 64x64/warp
    const int rowBase = blockIdx.y * 128;
    const int colBase = blockIdx.x * 128;

    auto load_chunk = [&](int ci, int buf) {
        const int k0 = ci * 64;
        #pragma unroll
        for (int a = 0; a < 2; a++) {
            const __half* src = (a == 0) ? Ah : Bs;
            const int gRow = (a == 0) ? rowBase : colBase;
            const uint32_t mbase = sb + buf * BUFB + a * MATB;
            #pragma unroll
            for (int it = 0; it < 8; it++) {
                int idx = it * 128 + tid;        // 0..1023
                int row = idx >> 3, seg = idx & 7;
                cp16(mbase + (uint32_t)(row * PK + seg * 8) * 2,
                     src + (size_t)(gRow + row) * 1024 + k0 + seg * 8);
            }
        }
        CP_COMMIT();
    };

    float acc[4][8][4];
    #pragma unroll
    for (int mi = 0; mi < 4; mi++)
        #pragma unroll
        for (int ni = 0; ni < 8; ni++)
            #pragma unroll
            for (int j = 0; j < 4; j++) acc[mi][ni][j] = 0.f;

    load_chunk(0, 0);

    for (int ci = 0; ci < NCHUNK; ci++) {
        const int buf = ci & 1;
        CP_WAIT0();
        __syncthreads();
        // Safe: every warp passed the barrier after finishing its reads of
        // buf^1 (iteration ci-1), so prefetching into buf^1 cannot race.
        if (ci + 1 < NCHUNK) load_chunk(ci + 1, buf ^ 1);

        const uint32_t aBase = sb + buf * BUFB;
        const uint32_t bBase = sb + buf * BUFB + MATB;

        #pragma unroll
        for (int ks = 0; ks < 4; ks++) {
            // B fragments: 64 columns (8 n8 tiles)
            uint32_t bh[8][2];
            const int bcol = ks * 16 + ((lane >> 3) & 1) * 8;
            #pragma unroll
            for (int np = 0; np < 4; np++) {
                int nr = wn * 64 + np * 16 + ((lane >> 4) & 1) * 8 + (lane & 7);
                ldsm_x4_b(bh[2 * np], bh[2 * np + 1],
                          bBase + (uint32_t)(nr * PK + bcol) * 2);
            }
            const int acol = ks * 16 + (lane >> 4) * 8;
            #pragma unroll
            for (int mi = 0; mi < 4; mi++) {
                uint32_t ah[4];
                int r = wm * 64 + mi * 16 + (lane & 15);
                ldsm_x4(ah, aBase + (uint32_t)(r * PK + acol) * 2);
                #pragma unroll
                for (int ni = 0; ni < 8; ni++)
                    mma_f16(acc[mi][ni], ah, bh[ni]);
            }
        }
    }

    const int rBase = rowBase + wm * 64 + (lane >> 2);
    const int cBase = colBase + wn * 64 + (lane & 3) * 2;
    #pragma unroll
    for (int mi = 0; mi < 4; mi++) {
        #pragma unroll
        for (int half = 0; half < 2; half++) {
            const int m = rBase + mi * 16 + half * 8;
            #pragma unroll
            for (int ni = 0; ni < 8; ni++) {
                const int n = cBase + ni * 8;
                float c0 = acc[mi][ni][half * 2 + 0];
                float c1 = acc[mi][ni][half * 2 + 1];
                if (mode == 0) {
                    int t = n >> 10, rem = n & 1023, h = rem >> 6, hd = rem & 63;
                    int b = m >> 9, nn = m & 511;
                    size_t idx = ((((size_t)b * 16 + h) * 512 + nn) * 64 + hd);
                    if (t == 0) {
                        *(uint32_t*)(g_q + idx) = pack_h16(c0 * 0.125f, c1 * 0.125f);
                    } else if (t == 1) {
                        *(uint32_t*)(g_k + idx) = pack_h16(c0, c1);
                    } else {
                        *(uint32_t*)(g_v + idx) = pack_h16(c0, c1);
                    }
                } else {
                    float* dst = Cout + (size_t)m * 1024 + n;
                    *(float2*)dst = make_float2(c0 + bias[n], c1 + bias[n + 1]);
                }
            }
        }
    }
}

// ---------------------------------------------------------------------------
// HMMA flash attention. CTA: 128 q rows, 8 warps x 16 rows, KV tiles of 64,
// double-buffered cp.async, single sync per tile. S = Q*K; O += P*V (1 pass).
// Only the column mask bias matters (row bias cancels in softmax).
// ---------------------------------------------------------------------------
#define PKV 72
#define KVMAT (64 * PKV * 2)          // 9216 B
#define KVBUF (2 * KVMAT)             // 18432 B (K, V)
#define ASMEM (2 * KVBUF + 512)       // + 2x 256B mask slots

__global__ __launch_bounds__(256)
void attn_hmma(const float* __restrict__ mask)
{
    extern __shared__ char smem[];
    const uint32_t sb = smem_u32(smem);
    const int b = blockIdx.z, h = blockIdx.y;
    const int tid = threadIdx.x;
    const int wid = tid >> 5, lane = tid & 31;

    const size_t base_bh = ((size_t)b * 16 + h) * 512 * 64;
    const __half* Qg = g_q + base_bh;
    const __half* Kg = g_k + base_bh;
    const __half* Vg = g_v + base_bh;

    const int r0 = blockIdx.x * 128 + wid * 16 + (lane >> 2);
    uint32_t qh[4][4];
    #pragma unroll
    for (int ks = 0; ks < 4; ks++) {
        const int c0 = ks * 16 + 2 * (lane & 3);
        qh[ks][0] = *(const uint32_t*)(Qg + (size_t)r0 * 64 + c0);
        qh[ks][1] = *(const uint32_t*)(Qg + (size_t)(r0 + 8) * 64 + c0);
        qh[ks][2] = *(const uint32_t*)(Qg + (size_t)r0 * 64 + c0 + 8);
        qh[ks][3] = *(const uint32_t*)(Qg + (size_t)(r0 + 8) * 64 + c0 + 8);
    }

    float acc_o[8][4];
    #pragma unroll
    for (int ni = 0; ni < 8; ni++)
        #pragma unroll
        for (int j = 0; j < 4; j++) acc_o[ni][j] = 0.f;
    float m0 = -1e30f, m1 = -1e30f, l0 = 0.f, l1 = 0.f;

    const __half* srcs[2] = {Kg, Vg};
    auto load_tile = [&](int kt, int buf) {
        #pragma unroll
        for (int mm = 0; mm < 2; mm++) {
            const uint32_t mbase = sb + buf * KVBUF + mm * KVMAT;
            #pragma unroll
            for (int it = 0; it < 2; it++) {
                int idx = it * 256 + tid;
                int row = idx >> 3, seg = idx & 7;
                cp16(mbase + (uint32_t)(row * PKV + seg * 8) * 2,
                     srcs[mm] + (size_t)(kt + row) * 64 + seg * 8);
            }
        }
        if (tid < 16) {
            float4 mv = *(const float4*)(mask + b * 512 + kt + tid * 4);
            *(float4*)(smem + 2 * KVBUF + buf * 256 + tid * 16) = mv;
        }
        CP_COMMIT();
    };

    load_tile(0, 0);

    for (int t = 0; t < 8; t++) {
        const int buf = t & 1;
        CP_WAIT0();
        __syncthreads();
        if (t < 7) load_tile((t + 1) * 64, buf ^ 1);

        const uint32_t kb_h = sb + buf * KVBUF;
        const uint32_t vb_h = kb_h + KVMAT;
        const float* Msm = (const float*)(smem + 2 * KVBUF + buf * 256);

        float s[8][4];
        #pragma unroll
        for (int ni = 0; ni < 8; ni++)
            #pragma unroll
            for (int j = 0; j < 4; j++) s[ni][j] = 0.f;

        const int g = lane >> 3;
        #pragma unroll
        for (int ks = 0; ks < 4; ks++) {
            uint32_t kh[8][2];
            #pragma unroll
            for (int np = 0; np < 4; np++) {
                ldsm_x4(&kh[2 * np][0], kb_h +
                    (uint32_t)(((2 * np + (g >> 1)) * 8 + (lane & 7)) * PKV +
                               ks * 16 + (g & 1) * 8) * 2);
            }
            #pragma unroll
            for (int ni = 0; ni < 8; ni++)
                mma_f16(s[ni], qh[ks], kh[ni]);
        }

        float tmax0 = -1e30f, tmax1 = -1e30f;
        #pragma unroll
        for (int ni = 0; ni < 8; ni++) {
            float2 mv = *(const float2*)(Msm + ni * 8 + 2 * (lane & 3));
            s[ni][0] += mv.x; s[ni][1] += mv.y;
            s[ni][2] += mv.x; s[ni][3] += mv.y;
            tmax0 = fmaxf(tmax0, fmaxf(s[ni][0], s[ni][1]));
            tmax1 = fmaxf(tmax1, fmaxf(s[ni][2], s[ni][3]));
        }
        tmax0 = fmaxf(tmax0, __shfl_xor_sync(0xffffffffu, tmax0, 1));
        tmax0 = fmaxf(tmax0, __shfl_xor_sync(0xffffffffu, tmax0, 2));
        tmax1 = fmaxf(tmax1, __shfl_xor_sync(0xffffffffu, tmax1, 1));
        tmax1 = fmaxf(tmax1, __shfl_xor_sync(0xffffffffu, tmax1, 2));

        const float mn0 = fmaxf(m0, tmax0), mn1 = fmaxf(m1, tmax1);
        const float al0 = __expf(m0 - mn0), al1 = __expf(m1 - mn1);
        m0 = mn0; m1 = mn1;
        l0 *= al0; l1 *= al1;
        #pragma unroll
        for (int ni = 0; ni < 8; ni++) {
            acc_o[ni][0] *= al0; acc_o[ni][1] *= al0;
            acc_o[ni][2] *= al1; acc_o[ni][3] *= al1;
        }

        uint32_t pah[4][4];
        #pragma unroll
        for (int ni = 0; ni < 8; ni++) {
            float p0 = __expf(s[ni][0] - mn0);
            float p1 = __expf(s[ni][1] - mn0);
            float p2 = __expf(s[ni][2] - mn1);
            float p3 = __expf(s[ni][3] - mn1);
            l0 += p0 + p1; l1 += p2 + p3;
            const int ks = ni >> 1, half = ni & 1;
            pah[ks][half * 2 + 0] = pack_h16(p0, p1);
            pah[ks][half * 2 + 1] = pack_h16(p2, p3);
        }

        #pragma unroll
        for (int ks = 0; ks < 4; ks++) {
            uint32_t vh[8][2];
            #pragma unroll
            for (int np = 0; np < 4; np++) {
                ldsm_x4_t(&vh[2 * np][0], vb_h +
                    (uint32_t)((ks * 16 + (g & 1) * 8 + (lane & 7)) * PKV +
                               (2 * np + (g >> 1)) * 8) * 2);
            }
            #pragma unroll
            for (int ni = 0; ni < 8; ni++)
                mma_f16(acc_o[ni], pah[ks], vh[ni]);
        }
    }

    l0 += __shfl_xor_sync(0xffffffffu, l0, 1);
    l0 += __shfl_xor_sync(0xffffffffu, l0, 2);
    l1 += __shfl_xor_sync(0xffffffffu, l1, 1);
    l1 += __shfl_xor_sync(0xffffffffu, l1, 2);
    const float inv0 = 1.0f / l0, inv1 = 1.0f / l1;

    const size_t rowA = ((size_t)b * 512 + r0) * 1024 + h * 64;
    const size_t rowB = ((size_t)b * 512 + r0 + 8) * 1024 + h * 64;
    #pragma unroll
    for (int ni = 0; ni < 8; ni++) {
        const int hd = ni * 8 + 2 * (lane & 3);
        *(uint32_t*)(g_ao + rowA + hd) = pack_h16(acc_o[ni][0] * inv0, acc_o[ni][1] * inv0);
        *(uint32_t*)(g_ao + rowB + hd) = pack_h16(acc_o[ni][2] * inv1, acc_o[ni][3] * inv1);
    }
}

// ---------------------------------------------------------------------------
extern "C" void kernel_launch(void* const* d_in, const int* in_sizes, int n_in,
                              void* d_out, int out_size)
{
    const float* x = nullptr;
    const float* mask = nullptr;
    const float* wqkv = nullptr;
    const float* wproj = nullptr;
    const float* bproj = nullptr;

    for (int i = 0; i < n_in; i++) {
        switch (in_sizes[i]) {
            case 32 * 512 * 1024:  x     = (const float*)d_in[i]; break;
            case 32 * 512:         mask  = (const float*)d_in[i]; break;
            case 3 * 1024 * 1024:  wqkv  = (const float*)d_in[i]; break;
            case 1024 * 1024:      wproj = (const float*)d_in[i]; break;
            case 1024:             bproj = (const float*)d_in[i]; break;
            default: break;
        }
    }

    static bool attr_set = false;
    if (!attr_set) {
        cudaFuncSetAttribute(hmma_gemm, cudaFuncAttributeMaxDynamicSharedMemorySize, GSMEM);
        cudaFuncSetAttribute(attn_hmma, cudaFuncAttributeMaxDynamicSharedMemorySize, ASMEM);
        attr_set = true;
    }

    __half *x16, *wq, *wp, *ao;
    cudaGetSymbolAddress((void**)&x16, g_x16);
    cudaGetSymbolAddress((void**)&wq,  g_wq);
    cudaGetSymbolAddress((void**)&wp,  g_wp);
    cudaGetSymbolAddress((void**)&ao,  g_ao);

    // fp32 -> fp16 (one launch for all three inputs)
    cvt_all<<<(N4_X + N4_WQ + N4_WP + 255) / 256, 256>>>(x, wqkv, wproj);

    // QKV projection -> q/k/v fp16 (1-pass)
    hmma_gemm<<<dim3(24, 128), 128, GSMEM>>>(x16, wq, nullptr, nullptr, 0);
    // HMMA flash attention -> g_ao (single fp16)
    attn_hmma<<<dim3(4, 16, 32), 256, ASMEM>>>(mask);
    // Output projection + bias -> d_out (1-pass)
    hmma_gemm<<<dim3(8, 128), 128, GSMEM>>>(ao, wp, bproj, (float*)d_out, 1);
}

// round 17
// speedup vs baseline: 1.0213x; 1.0213x over previous
#include <cuda_runtime.h>
#include <cuda_fp16.h>
#include <cstdint>

// ===========================================================================
// Problem constants: B=32, N=512, C=1024, H=16, HD=64, SCALE=0.125
// compute_103 toolchain: no tcgen05; tensor cores via mma.sync (HMMA).
// Precision: ALL GEMMs 1-pass fp16 (measured rel_err 5.73e-4; gate 1e-3).
// Config: R14 base (64x32 warp tile, 256 thr, 2 CTAs/SM, BK=64, 1 bar/chunk)
// + batched fragment loads: all 6 ldsm per ks issued together, then 16 MMAs.
// ===========================================================================

__device__ __half g_q[16777216];                     // Q (pre-scaled 0.125)
__device__ __half g_k[16777216], g_v[16777216];
__device__ __half g_x16[16777216];                   // x [16384,1024] fp16
__device__ __half g_wq[3145728];                     // W_qkv fp16
__device__ __half g_wp[1048576];                     // W_proj fp16
__device__ __half g_ao[16777216];                    // attn out [B,N,C] fp16

// ---------------------------------------------------------------------------
// PTX helpers (plain sm_80+ PTX — safe under compute_103)
// ---------------------------------------------------------------------------
__device__ __forceinline__ uint32_t smem_u32(const void* p) {
    uint32_t a;
    asm("{ .reg .u64 t; cvta.to.shared.u64 t, %1; cvt.u32.u64 %0, t; }" : "=r"(a) : "l"(p));
    return a;
}
__device__ __forceinline__ void mma_f16(float* c, const uint32_t* a, const uint32_t* b) {
    asm volatile(
        "mma.sync.aligned.m16n8k16.row.col.f32.f16.f16.f32 "
        "{%0,%1,%2,%3}, {%4,%5,%6,%7}, {%8,%9}, {%0,%1,%2,%3};"
        : "+f"(c[0]), "+f"(c[1]), "+f"(c[2]), "+f"(c[3])
        : "r"(a[0]), "r"(a[1]), "r"(a[2]), "r"(a[3]), "r"(b[0]), "r"(b[1]));
}
__device__ __forceinline__ void ldsm_x4(uint32_t* r, uint32_t addr) {
    asm volatile("ldmatrix.sync.aligned.m8n8.x4.shared.b16 {%0,%1,%2,%3}, [%4];"
        : "=r"(r[0]), "=r"(r[1]), "=r"(r[2]), "=r"(r[3]) : "r"(addr));
}
__device__ __forceinline__ void ldsm_x4_b(uint32_t* r0, uint32_t* r1, uint32_t addr) {
    asm volatile("ldmatrix.sync.aligned.m8n8.x4.shared.b16 {%0,%1,%2,%3}, [%4];"
        : "=r"(r0[0]), "=r"(r0[1]), "=r"(r1[0]), "=r"(r1[1]) : "r"(addr));
}
__device__ __forceinline__ void ldsm_x4_t(uint32_t* r, uint32_t addr) {
    asm volatile("ldmatrix.sync.aligned.m8n8.x4.trans.shared.b16 {%0,%1,%2,%3}, [%4];"
        : "=r"(r[0]), "=r"(r[1]), "=r"(r[2]), "=r"(r[3]) : "r"(addr));
}
__device__ __forceinline__ void cp16(uint32_t saddr, const void* g) {
    asm volatile("cp.async.cg.shared.global [%0], [%1], 16;" :: "r"(saddr), "l"(g));
}
#define CP_COMMIT() asm volatile("cp.async.commit_group;" ::: "memory")
#define CP_WAIT0()  asm volatile("cp.async.wait_group 0;" ::: "memory")

__device__ __forceinline__ uint32_t pack_h16(float a, float b) {
    __half2 p = __floats2half2_rn(a, b);
    return *(uint32_t*)&p;
}

// ---------------------------------------------------------------------------
// fp32 -> fp16, all three inputs in one launch (range dispatch)
// ---------------------------------------------------------------------------
#define N4_X  4194304
#define N4_WQ 786432
#define N4_WP 262144
__global__ __launch_bounds__(256)
void cvt_all(const float* __restrict__ x,  const float* __restrict__ wq,
             const float* __restrict__ wp)
{
    int i = blockIdx.x * blockDim.x + threadIdx.x;
    const float* src; __half* dst; int j;
    if (i < N4_X)                 { src = x;  dst = g_x16; j = i; }
    else if (i < N4_X + N4_WQ)    { src = wq; dst = g_wq;  j = i - N4_X; }
    else if (i < N4_X + N4_WQ + N4_WP) { src = wp; dst = g_wp; j = i - N4_X - N4_WQ; }
    else return;
    float4 v = ((const float4*)src)[j];
    ((uint32_t*)dst)[2*j]   = pack_h16(v.x, v.y);
    ((uint32_t*)dst)[2*j+1] = pack_h16(v.z, v.w);
}

// ---------------------------------------------------------------------------
// HMMA GEMM (1-pass fp16): C[m,n] = sum_k A[m,k]*B[n,k]. K=1024.
// CTA 128x128, BK=64, 256 threads, 8 warps (2m x 4n), 64x32 per warp.
// Single __syncthreads per chunk. Per ks: batch 6 ldsm, then 16 MMAs.
// mode 0: scatter to q/k/v fp16. mode 1: +bias -> Cout fp32.
// ---------------------------------------------------------------------------
#define PK 72                        // 64 + 8 pad halves per row
#define MATB (128 * PK * 2)          // 18432 B per 128x64 tile
#define BUFB (2 * MATB)              // A + B tiles: 36864 B
#define GSMEM (2 * BUFB)             // double buffered: 73728 B
#define NCHUNK 16

__global__ __launch_bounds__(256, 2)
void hmma_gemm(const __half* __restrict__ Ah, const __half* __restrict__ Bs,
               const float* __restrict__ bias, float* __restrict__ Cout, int mode)
{
    extern __shared__ char smem[];
    const uint32_t sb = smem_u32(smem);
    const int tid  = threadIdx.x;
    const int wid  = tid >> 5, lane = tid & 31;
    const int wm   = wid >> 2, wn = wid & 3;          // 2 x 4 warp grid, 64x32/warp
    const int rowBase = blockIdx.y * 128;
    const int colBase = blockIdx.x * 128;

    auto load_chunk = [&](int ci, int buf) {
        const int k0 = ci * 64;
        #pragma unroll
        for (int a = 0; a < 2; a++) {
            const __half* src = (a == 0) ? Ah : Bs;
            const int gRow = (a == 0) ? rowBase : colBase;
            const uint32_t mbase = sb + buf * BUFB + a * MATB;
            #pragma unroll
            for (int it = 0; it < 4; it++) {
                int idx = it * 256 + tid;        // 0..1023
                int row = idx >> 3, seg = idx & 7;
                cp16(mbase + (uint32_t)(row * PK + seg * 8) * 2,
                     src + (size_t)(gRow + row) * 1024 + k0 + seg * 8);
            }
        }
        CP_COMMIT();
    };

    float acc[4][4][4];
    #pragma unroll
    for (int mi = 0; mi < 4; mi++)
        #pragma unroll
        for (int ni = 0; ni < 4; ni++)
            #pragma unroll
            for (int j = 0; j < 4; j++) acc[mi][ni][j] = 0.f;

    load_chunk(0, 0);

    for (int ci = 0; ci < NCHUNK; ci++) {
        const int buf = ci & 1;
        CP_WAIT0();
        __syncthreads();
        // Safe: every warp passed the barrier after finishing its reads of
        // buf^1 (iteration ci-1), so prefetching into buf^1 cannot race.
        if (ci + 1 < NCHUNK) load_chunk(ci + 1, buf ^ 1);

        const uint32_t aBase = sb + buf * BUFB;
        const uint32_t bBase = sb + buf * BUFB + MATB;

        #pragma unroll
        for (int ks = 0; ks < 4; ks++) {
            // Batch ALL fragment loads for this k16 slice (2 B + 4 A ldsm),
            // so their latencies pipeline together, then run 16 MMAs clean.
            uint32_t bh[4][2], ah[4][4];
            const int bcol = ks * 16 + ((lane >> 3) & 1) * 8;
            #pragma unroll
            for (int np = 0; np < 2; np++) {
                int nr = wn * 32 + np * 16 + ((lane >> 4) & 1) * 8 + (lane & 7);
                ldsm_x4_b(bh[2 * np], bh[2 * np + 1],
                          bBase + (uint32_t)(nr * PK + bcol) * 2);
            }
            const int acol = ks * 16 + (lane >> 4) * 8;
            #pragma unroll
            for (int mi = 0; mi < 4; mi++) {
                int r = wm * 64 + mi * 16 + (lane & 15);
                ldsm_x4(ah[mi], aBase + (uint32_t)(r * PK + acol) * 2);
            }
            #pragma unroll
            for (int mi = 0; mi < 4; mi++)
                #pragma unroll
                for (int ni = 0; ni < 4; ni++)
                    mma_f16(acc[mi][ni], ah[mi], bh[ni]);
        }
    }

    const int rBase = rowBase + wm * 64 + (lane >> 2);
    const int cBase = colBase + wn * 32 + (lane & 3) * 2;
    #pragma unroll
    for (int mi = 0; mi < 4; mi++) {
        #pragma unroll
        for (int half = 0; half < 2; half++) {
            const int m = rBase + mi * 16 + half * 8;
            #pragma unroll
            for (int ni = 0; ni < 4; ni++) {
                const int n = cBase + ni * 8;
                float c0 = acc[mi][ni][half * 2 + 0];
                float c1 = acc[mi][ni][half * 2 + 1];
                if (mode == 0) {
                    int t = n >> 10, rem = n & 1023, h = rem >> 6, hd = rem & 63;
                    int b = m >> 9, nn = m & 511;
                    size_t idx = ((((size_t)b * 16 + h) * 512 + nn) * 64 + hd);
                    if (t == 0) {
                        *(uint32_t*)(g_q + idx) = pack_h16(c0 * 0.125f, c1 * 0.125f);
                    } else if (t == 1) {
                        *(uint32_t*)(g_k + idx) = pack_h16(c0, c1);
                    } else {
                        *(uint32_t*)(g_v + idx) = pack_h16(c0, c1);
                    }
                } else {
                    float* dst = Cout + (size_t)m * 1024 + n;
                    *(float2*)dst = make_float2(c0 + bias[n], c1 + bias[n + 1]);
                }
            }
        }
    }
}

// ---------------------------------------------------------------------------
// HMMA flash attention. CTA: 128 q rows, 8 warps x 16 rows, KV tiles of 64,
// double-buffered cp.async, single sync per tile. S = Q*K; O += P*V (1 pass).
// Only the column mask bias matters (row bias cancels in softmax).
// ---------------------------------------------------------------------------
#define PKV 72
#define KVMAT (64 * PKV * 2)          // 9216 B
#define KVBUF (2 * KVMAT)             // 18432 B (K, V)
#define ASMEM (2 * KVBUF + 512)       // + 2x 256B mask slots

__global__ __launch_bounds__(256)
void attn_hmma(const float* __restrict__ mask)
{
    extern __shared__ char smem[];
    const uint32_t sb = smem_u32(smem);
    const int b = blockIdx.z, h = blockIdx.y;
    const int tid = threadIdx.x;
    const int wid = tid >> 5, lane = tid & 31;

    const size_t base_bh = ((size_t)b * 16 + h) * 512 * 64;
    const __half* Qg = g_q + base_bh;
    const __half* Kg = g_k + base_bh;
    const __half* Vg = g_v + base_bh;

    const int r0 = blockIdx.x * 128 + wid * 16 + (lane >> 2);
    uint32_t qh[4][4];
    #pragma unroll
    for (int ks = 0; ks < 4; ks++) {
        const int c0 = ks * 16 + 2 * (lane & 3);
        qh[ks][0] = *(const uint32_t*)(Qg + (size_t)r0 * 64 + c0);
        qh[ks][1] = *(const uint32_t*)(Qg + (size_t)(r0 + 8) * 64 + c0);
        qh[ks][2] = *(const uint32_t*)(Qg + (size_t)r0 * 64 + c0 + 8);
        qh[ks][3] = *(const uint32_t*)(Qg + (size_t)(r0 + 8) * 64 + c0 + 8);
    }

    float acc_o[8][4];
    #pragma unroll
    for (int ni = 0; ni < 8; ni++)
        #pragma unroll
        for (int j = 0; j < 4; j++) acc_o[ni][j] = 0.f;
    float m0 = -1e30f, m1 = -1e30f, l0 = 0.f, l1 = 0.f;

    const __half* srcs[2] = {Kg, Vg};
    auto load_tile = [&](int kt, int buf) {
        #pragma unroll
        for (int mm = 0; mm < 2; mm++) {
            const uint32_t mbase = sb + buf * KVBUF + mm * KVMAT;
            #pragma unroll
            for (int it = 0; it < 2; it++) {
                int idx = it * 256 + tid;
                int row = idx >> 3, seg = idx & 7;
                cp16(mbase + (uint32_t)(row * PKV + seg * 8) * 2,
                     srcs[mm] + (size_t)(kt + row) * 64 + seg * 8);
            }
        }
        if (tid < 16) {
            float4 mv = *(const float4*)(mask + b * 512 + kt + tid * 4);
            *(float4*)(smem + 2 * KVBUF + buf * 256 + tid * 16) = mv;
        }
        CP_COMMIT();
    };

    load_tile(0, 0);

    for (int t = 0; t < 8; t++) {
        const int buf = t & 1;
        CP_WAIT0();
        __syncthreads();
        if (t < 7) load_tile((t + 1) * 64, buf ^ 1);

        const uint32_t kb_h = sb + buf * KVBUF;
        const uint32_t vb_h = kb_h + KVMAT;
        const float* Msm = (const float*)(smem + 2 * KVBUF + buf * 256);

        float s[8][4];
        #pragma unroll
        for (int ni = 0; ni < 8; ni++)
            #pragma unroll
            for (int j = 0; j < 4; j++) s[ni][j] = 0.f;

        const int g = lane >> 3;
        #pragma unroll
        for (int ks = 0; ks < 4; ks++) {
            uint32_t kh[8][2];
            #pragma unroll
            for (int np = 0; np < 4; np++) {
                ldsm_x4(&kh[2 * np][0], kb_h +
                    (uint32_t)(((2 * np + (g >> 1)) * 8 + (lane & 7)) * PKV +
                               ks * 16 + (g & 1) * 8) * 2);
            }
            #pragma unroll
            for (int ni = 0; ni < 8; ni++)
                mma_f16(s[ni], qh[ks], kh[ni]);
        }

        float tmax0 = -1e30f, tmax1 = -1e30f;
        #pragma unroll
        for (int ni = 0; ni < 8; ni++) {
            float2 mv = *(const float2*)(Msm + ni * 8 + 2 * (lane & 3));
            s[ni][0] += mv.x; s[ni][1] += mv.y;
            s[ni][2] += mv.x; s[ni][3] += mv.y;
            tmax0 = fmaxf(tmax0, fmaxf(s[ni][0], s[ni][1]));
            tmax1 = fmaxf(tmax1, fmaxf(s[ni][2], s[ni][3]));
        }
        tmax0 = fmaxf(tmax0, __shfl_xor_sync(0xffffffffu, tmax0, 1));
        tmax0 = fmaxf(tmax0, __shfl_xor_sync(0xffffffffu, tmax0, 2));
        tmax1 = fmaxf(tmax1, __shfl_xor_sync(0xffffffffu, tmax1, 1));
        tmax1 = fmaxf(tmax1, __shfl_xor_sync(0xffffffffu, tmax1, 2));

        const float mn0 = fmaxf(m0, tmax0), mn1 = fmaxf(m1, tmax1);
        const float al0 = __expf(m0 - mn0), al1 = __expf(m1 - mn1);
        m0 = mn0; m1 = mn1;
        l0 *= al0; l1 *= al1;
        #pragma unroll
        for (int ni = 0; ni < 8; ni++) {
            acc_o[ni][0] *= al0; acc_o[ni][1] *= al0;
            acc_o[ni][2] *= al1; acc_o[ni][3] *= al1;
        }

        uint32_t pah[4][4];
        #pragma unroll
        for (int ni = 0; ni < 8; ni++) {
            float p0 = __expf(s[ni][0] - mn0);
            float p1 = __expf(s[ni][1] - mn0);
            float p2 = __expf(s[ni][2] - mn1);
            float p3 = __expf(s[ni][3] - mn1);
            l0 += p0 + p1; l1 += p2 + p3;
            const int ks = ni >> 1, half = ni & 1;
            pah[ks][half * 2 + 0] = pack_h16(p0, p1);
            pah[ks][half * 2 + 1] = pack_h16(p2, p3);
        }

        #pragma unroll
        for (int ks = 0; ks < 4; ks++) {
            uint32_t vh[8][2];
            #pragma unroll
            for (int np = 0; np < 4; np++) {
                ldsm_x4_t(&vh[2 * np][0], vb_h +
                    (uint32_t)((ks * 16 + (g & 1) * 8 + (lane & 7)) * PKV +
                               (2 * np + (g >> 1)) * 8) * 2);
            }
            #pragma unroll
            for (int ni = 0; ni < 8; ni++)
                mma_f16(acc_o[ni], pah[ks], vh[ni]);
        }
    }

    l0 += __shfl_xor_sync(0xffffffffu, l0, 1);
    l0 += __shfl_xor_sync(0xffffffffu, l0, 2);
    l1 += __shfl_xor_sync(0xffffffffu, l1, 1);
    l1 += __shfl_xor_sync(0xffffffffu, l1, 2);
    const float inv0 = 1.0f / l0, inv1 = 1.0f / l1;

    const size_t rowA = ((size_t)b * 512 + r0) * 1024 + h * 64;
    const size_t rowB = ((size_t)b * 512 + r0 + 8) * 1024 + h * 64;
    #pragma unroll
    for (int ni = 0; ni < 8; ni++) {
        const int hd = ni * 8 + 2 * (lane & 3);
        *(uint32_t*)(g_ao + rowA + hd) = pack_h16(acc_o[ni][0] * inv0, acc_o[ni][1] * inv0);
        *(uint32_t*)(g_ao + rowB + hd) = pack_h16(acc_o[ni][2] * inv1, acc_o[ni][3] * inv1);
    }
}

// ---------------------------------------------------------------------------
extern "C" void kernel_launch(void* const* d_in, const int* in_sizes, int n_in,
                              void* d_out, int out_size)
{
    const float* x = nullptr;
    const float* mask = nullptr;
    const float* wqkv = nullptr;
    const float* wproj = nullptr;
    const float* bproj = nullptr;

    for (int i = 0; i < n_in; i++) {
        switch (in_sizes[i]) {
            case 32 * 512 * 1024:  x     = (const float*)d_in[i]; break;
            case 32 * 512:         mask  = (const float*)d_in[i]; break;
            case 3 * 1024 * 1024:  wqkv  = (const float*)d_in[i]; break;
            case 1024 * 1024:      wproj = (const float*)d_in[i]; break;
            case 1024:             bproj = (const float*)d_in[i]; break;
            default: break;
        }
    }

    static bool attr_set = false;
    if (!attr_set) {
        cudaFuncSetAttribute(hmma_gemm, cudaFuncAttributeMaxDynamicSharedMemorySize, GSMEM);
        cudaFuncSetAttribute(attn_hmma, cudaFuncAttributeMaxDynamicSharedMemorySize, ASMEM);
        attr_set = true;
    }

    __half *x16, *wq, *wp, *ao;
    cudaGetSymbolAddress((void**)&x16, g_x16);
    cudaGetSymbolAddress((void**)&wq,  g_wq);
    cudaGetSymbolAddress((void**)&wp,  g_wp);
    cudaGetSymbolAddress((void**)&ao,  g_ao);

    // fp32 -> fp16 (one launch for all three inputs)
    cvt_all<<<(N4_X + N4_WQ + N4_WP + 255) / 256, 256>>>(x, wqkv, wproj);

    // QKV projection -> q/k/v fp16 (1-pass)
    hmma_gemm<<<dim3(24, 128), 256, GSMEM>>>(x16, wq, nullptr, nullptr, 0);
    // HMMA flash attention -> g_ao (single fp16)
    attn_hmma<<<dim3(4, 16, 32), 256, ASMEM>>>(mask);
    // Output projection + bias -> d_out (1-pass)
    hmma_gemm<<<dim3(8, 128), 256, GSMEM>>>(ao, wp, bproj, (float*)d_out, 1);
}